// round 13
// baseline (speedup 1.0000x reference)
#include <cuda_runtime.h>
#include <cuda_fp16.h>
#include <cstdint>
#include <math.h>

#define B_   4
#define S_   2048
#define H_   1024
#define F_   4096
#define NTOK (B_ * S_)   // 8192

// ---------------------------------------------------------------------------
// Scratch (static device globals)
// ---------------------------------------------------------------------------
__device__ __half g_xh[(size_t)NTOK * H_];
__device__ __half g_qk[(size_t)NTOK * 2 * H_];     // [8192, 2048]: q | k
__device__ __half g_s16[(size_t)B_ * S_ * S_];
__device__ __half g_a16[(size_t)NTOK * H_];
__device__ __half g_h16[(size_t)NTOK * F_];
__device__ float  g_y[(size_t)NTOK * H_];
__device__ __half g_wqkt[(size_t)2 * H_ * H_];     // [2048, 1024]: wq^T | wk^T
__device__ __half g_wvt[(size_t)H_ * H_];
__device__ __half g_w1t[(size_t)H_ * F_];
__device__ __half g_w2t[(size_t)F_ * H_];
__device__ __half g_vt[(size_t)H_ * NTOK];         // [1024, 8192] V^T, all batches
__device__ float  g_qkb[2 * H_];

// ---------------------------------------------------------------------------
// Helpers
// ---------------------------------------------------------------------------
__device__ __forceinline__ uint32_t smem_u32(const void* p) {
    uint32_t a;
    asm("{ .reg .u64 t; cvta.to.shared.u64 t, %1; cvt.u32.u64 %0, t; }" : "=r"(a) : "l"(p));
    return a;
}
__device__ __forceinline__ void cp16(uint32_t s, const void* g) {
    asm volatile("cp.async.cg.shared.global [%0], [%1], 16;" :: "r"(s), "l"(g) : "memory");
}
#define CP_COMMIT() asm volatile("cp.async.commit_group;" ::: "memory")
#define CP_WAIT3()  asm volatile("cp.async.wait_group 3;" ::: "memory")

__device__ __forceinline__ void mma16(float c[4], const uint32_t a[4], const uint32_t b[2]) {
    asm volatile("mma.sync.aligned.m16n8k16.row.col.f32.f16.f16.f32 "
                 "{%0,%1,%2,%3}, {%4,%5,%6,%7}, {%8,%9}, {%0,%1,%2,%3};"
                 : "+f"(c[0]), "+f"(c[1]), "+f"(c[2]), "+f"(c[3])
                 : "r"(a[0]), "r"(a[1]), "r"(a[2]), "r"(a[3]), "r"(b[0]), "r"(b[1]));
}
__device__ __forceinline__ void ldsm4(uint32_t r[4], uint32_t addr) {
    asm volatile("ldmatrix.sync.aligned.m8n8.x4.shared.b16 {%0,%1,%2,%3}, [%4];"
                 : "=r"(r[0]), "=r"(r[1]), "=r"(r[2]), "=r"(r[3]) : "r"(addr));
}

// ---------------------------------------------------------------------------
// FP16 tensor-core GEMM (fp32 accum), cp.async 5-stage pipeline, ldmatrix:
//   acc = alpha * A[M,K] * Bw[N,K]^T (+bias[N]) (+biasM[M]) (+res fp16) (relu)
//   outputs: C16 (fp16) if O16, C32 (fp32) if O32
// CTA tile 128x128, BK=32, 4 warps (2x2), warp tile 64x64, 128 threads,
// 2 CTAs/SM. Co-resident CTAs anti-phased via entry nanosleep stagger.
// M,N mult of 128, K mult of 32. Batched over blockIdx.z.
// Smem: 5 stages x (128+128) rows x 80 B = 102400 B (204.8 KB/SM for 2 CTAs).
// ---------------------------------------------------------------------------
#define ROWB 80                                  // bytes per smem row (32 fp16 + 8 pad)
#define STAGE_B  ((128 + 128) * ROWB)            // 20480
#define NSTAGE 5
#define SMEM_B   (NSTAGE * STAGE_B)              // 102400

template <bool BIAS, bool RELU, bool RES, bool BIASM, bool O16, bool O32>
__global__ __launch_bounds__(128, 2) void tgemm(
    const __half* __restrict__ A, const __half* __restrict__ Bw,
    const float* __restrict__ bias, const __half* __restrict__ res,
    __half* __restrict__ C16, float* __restrict__ C32,
    int K, int lda, int ldb, int ldc,
    size_t sA, size_t sB, size_t sC, float alpha)
{
    extern __shared__ uint32_t smem[];
    const uint32_t sbase = smem_u32(smem);

    // Anti-phase stagger: co-resident slot-1 CTAs start ~1/2 k-tile later so
    // their overhead phases (barrier+LDSM+cp.async) cover the peer's MMA burst.
    {
        const int lin = blockIdx.x + gridDim.x * (blockIdx.y + gridDim.y * blockIdx.z);
        if ((lin / 152) & 1) __nanosleep(500);
    }

    const int tid  = threadIdx.x;
    const int wid  = tid >> 5, lane = tid & 31;
    const int g    = lane >> 2, t4 = lane & 3;
    const int warpM = wid >> 1, warpN = wid & 1;

    const int z = blockIdx.z;
    A  += (size_t)z * sA;
    Bw += (size_t)z * sB;
    const __half* Rp = RES ? (res + (size_t)z * sC) : nullptr;

    const int n0 = blockIdx.x << 7, m0 = blockIdx.y << 7;
    const __half* Ap = A  + (size_t)m0 * lda;
    const __half* Bp = Bw + (size_t)n0 * ldb;

    const int KT = K >> 5;

    // per-thread cp.async source base pointers (row/chunk fixed per thread)
    const int cRow = tid >> 2, cCh = tid & 3;
    const __half* aSrc0 = Ap + (size_t)cRow * lda + cCh * 8;
    const __half* aSrc1 = Ap + (size_t)(cRow + 32) * lda + cCh * 8;
    const __half* aSrc2 = Ap + (size_t)(cRow + 64) * lda + cCh * 8;
    const __half* aSrc3 = Ap + (size_t)(cRow + 96) * lda + cCh * 8;
    const __half* bSrc0 = Bp + (size_t)cRow * ldb + cCh * 8;
    const __half* bSrc1 = Bp + (size_t)(cRow + 32) * ldb + cCh * 8;
    const __half* bSrc2 = Bp + (size_t)(cRow + 64) * ldb + cCh * 8;
    const __half* bSrc3 = Bp + (size_t)(cRow + 96) * ldb + cCh * 8;
    const uint32_t dOffA = (uint32_t)(cRow * ROWB + cCh * 16);
    const uint32_t rowStep = 32 * ROWB;

    auto issue = [&](int kt) {
        const uint32_t s = sbase + (uint32_t)(kt % NSTAGE) * STAGE_B;
        const int kb = kt << 5;
        cp16(s + dOffA,                aSrc0 + kb);
        cp16(s + dOffA + rowStep,      aSrc1 + kb);
        cp16(s + dOffA + 2 * rowStep,  aSrc2 + kb);
        cp16(s + dOffA + 3 * rowStep,  aSrc3 + kb);
        const uint32_t sB2 = s + (uint32_t)(128 * ROWB);
        cp16(sB2 + dOffA,               bSrc0 + kb);
        cp16(sB2 + dOffA + rowStep,     bSrc1 + kb);
        cp16(sB2 + dOffA + 2 * rowStep, bSrc2 + kb);
        cp16(sB2 + dOffA + 3 * rowStep, bSrc3 + kb);
    };

    // ldmatrix per-lane source offsets (bytes)
    const int aRowOff = (((lane >> 3) & 1) << 3) + (lane & 7);
    const int aKb     = (lane >> 4) << 4;                 // 0 or 16 bytes
    const int bRowOff = ((lane >> 4) << 3) + (lane & 7);
    const int bKb     = ((lane >> 3) & 1) << 4;

    const uint32_t aLane = sbase + (uint32_t)((warpM * 64 + aRowOff) * ROWB + aKb);
    const uint32_t bLane = sbase + (uint32_t)(128 * ROWB)
        + (uint32_t)((warpN * 64 + bRowOff) * ROWB + bKb);

    float acc[4][8][4];
#pragma unroll
    for (int mt = 0; mt < 4; mt++)
#pragma unroll
        for (int nt = 0; nt < 8; nt++)
#pragma unroll
            for (int i = 0; i < 4; i++) acc[mt][nt][i] = 0.0f;

    // prologue: stages 0..3 in flight
    issue(0); CP_COMMIT();
    issue(1); CP_COMMIT();
    issue(2); CP_COMMIT();
    issue(3); CP_COMMIT();

    for (int kt = 0; kt < KT; kt++) {
        CP_WAIT3();
        __syncthreads();

        if (kt + 4 < KT) issue(kt + 4);
        CP_COMMIT();

        const uint32_t stOff = (uint32_t)((kt % NSTAGE) * STAGE_B);

        // hoist ALL fragment loads (both k16 slices) ahead of the MMA burst
        uint32_t afr[2][4][4], bfr[2][8][2];
#pragma unroll
        for (int ks = 0; ks < 2; ks++) {
#pragma unroll
            for (int mt = 0; mt < 4; mt++)
                ldsm4(afr[ks][mt], aLane + stOff + (uint32_t)(mt * 16 * ROWB + ks * 32));
#pragma unroll
            for (int p = 0; p < 4; p++) {
                uint32_t r[4];
                ldsm4(r, bLane + stOff + (uint32_t)(p * 16 * ROWB + ks * 32));
                bfr[ks][2 * p][0] = r[0]; bfr[ks][2 * p][1] = r[1];
                bfr[ks][2 * p + 1][0] = r[2]; bfr[ks][2 * p + 1][1] = r[3];
            }
        }
#pragma unroll
        for (int ks = 0; ks < 2; ks++)
#pragma unroll
            for (int mt = 0; mt < 4; mt++)
#pragma unroll
                for (int nt = 0; nt < 8; nt++)
                    mma16(acc[mt][nt], afr[ks][mt], bfr[ks][nt]);
    }

    // --- fused epilogue ---
    __half* Cp16 = O16 ? (C16 + (size_t)z * sC) : nullptr;
    float*  Cp32 = O32 ? (C32 + (size_t)z * sC) : nullptr;
    const int rbase = m0 + warpM * 64;
    const int cbase = n0 + warpN * 64;
#pragma unroll
    for (int mt = 0; mt < 4; mt++) {
#pragma unroll
        for (int nt = 0; nt < 8; nt++) {
            const int col = cbase + nt * 8 + (t4 << 1);
            float bx = 0.f, by = 0.f;
            if (BIAS) {
                float2 bb = *(const float2*)(bias + col);
                bx = bb.x; by = bb.y;
            }
#pragma unroll
            for (int hh = 0; hh < 2; hh++) {
                const int row = rbase + mt * 16 + g + hh * 8;
                float v0 = acc[mt][nt][hh * 2 + 0] * alpha;
                float v1 = acc[mt][nt][hh * 2 + 1] * alpha;
                if (BIAS) { v0 += bx; v1 += by; }
                if (BIASM) { const float bm = bias[row]; v0 += bm; v1 += bm; }
                if (RES) {
                    const __half2 rr = *(const __half2*)(Rp + (size_t)row * ldc + col);
                    const float2 rf = __half22float2(rr);
                    v0 += rf.x; v1 += rf.y;
                }
                if (RELU) { v0 = fmaxf(v0, 0.f); v1 = fmaxf(v1, 0.f); }
                if (O16)
                    *(__half2*)(Cp16 + (size_t)row * ldc + col) = __floats2half2_rn(v0, v1);
                if (O32) {
                    float2 o; o.x = v0; o.y = v1;
                    *(float2*)(Cp32 + (size_t)row * ldc + col) = o;
                }
            }
        }
    }
}

// ---------------------------------------------------------------------------
// x (fp32) -> fp16
// ---------------------------------------------------------------------------
__global__ __launch_bounds__(256) void tohalf_k(const float* __restrict__ in,
                                                __half* __restrict__ out)
{
    const size_t i = ((size_t)blockIdx.x * 256 + threadIdx.x) * 4;
    float4 v = *(const float4*)(in + i);
    __half2* o = (__half2*)(out + i);
    o[0] = __floats2half2_rn(v.x, v.y);
    o[1] = __floats2half2_rn(v.z, v.w);
}

// ---------------------------------------------------------------------------
// Concat two H_-vectors (bias) into one 2H_ vector
// ---------------------------------------------------------------------------
__global__ __launch_bounds__(256) void catbias_k(const float* __restrict__ a,
                                                 const float* __restrict__ b,
                                                 float* __restrict__ out)
{
    const int i = blockIdx.x * 256 + threadIdx.x;
    out[i] = (i < H_) ? a[i] : b[i - H_];
}

// ---------------------------------------------------------------------------
// Transpose fp32 src [R,C] -> fp16 dst [C,R]
// ---------------------------------------------------------------------------
__global__ __launch_bounds__(256) void transpose_k(const float* __restrict__ src,
                                                   __half* __restrict__ dst, int R, int C)
{
    __shared__ float t[32][33];
    const int bx = blockIdx.x << 5, by = blockIdx.y << 5;
    const int tx = threadIdx.x & 31, ty = (threadIdx.x >> 5) << 2;
#pragma unroll
    for (int j = 0; j < 4; j++)
        t[ty + j][tx] = src[(size_t)(by + ty + j) * C + bx + tx];
    __syncthreads();
#pragma unroll
    for (int j = 0; j < 4; j++)
        dst[(size_t)(bx + ty + j) * R + by + tx] = __float2half_rn(t[tx][ty + j]);
}

// ---------------------------------------------------------------------------
// Row softmax (S_ wide) on fp16 scores with fp32 mask; in-place fp16
// ---------------------------------------------------------------------------
__global__ __launch_bounds__(256) void softmax_k(__half* __restrict__ s,
                                                 const float* __restrict__ mask)
{
    const int row = blockIdx.x;
    const int q   = row & (S_ - 1);
    __half2* p = (__half2*)(s + (size_t)row * S_);
    const float* mrow = mask + (size_t)q * S_;
    const int tid = threadIdx.x;
    __shared__ float red[256];

    float vals[8];
    float vmax = -3.0e38f;
#pragma unroll
    for (int i = 0; i < 4; i++) {
        const int idx = tid + i * 256;          // half2 index
        const float2 v2 = __half22float2(p[idx]);
        const float m0 = mrow[idx * 2], m1 = mrow[idx * 2 + 1];
        const float a = v2.x + m0, b = v2.y + m1;
        vals[2 * i] = a; vals[2 * i + 1] = b;
        vmax = fmaxf(vmax, fmaxf(a, b));
    }
    red[tid] = vmax; __syncthreads();
    for (int o = 128; o > 0; o >>= 1) {
        if (tid < o) red[tid] = fmaxf(red[tid], red[tid + o]);
        __syncthreads();
    }
    vmax = red[0]; __syncthreads();
    float sum = 0.0f;
#pragma unroll
    for (int i = 0; i < 8; i++) { const float e = __expf(vals[i] - vmax); vals[i] = e; sum += e; }
    red[tid] = sum; __syncthreads();
    for (int o = 128; o > 0; o >>= 1) {
        if (tid < o) red[tid] += red[tid + o];
        __syncthreads();
    }
    const float inv = 1.0f / red[0];
#pragma unroll
    for (int i = 0; i < 4; i++)
        p[tid + i * 256] = __floats2half2_rn(vals[2 * i] * inv, vals[2 * i + 1] * inv);
}

// ---------------------------------------------------------------------------
// LayerNorm (H_=1024)
// ---------------------------------------------------------------------------
__global__ __launch_bounds__(256) void ln_k(const float* __restrict__ y,
                                            const float* __restrict__ gamma,
                                            const float* __restrict__ beta,
                                            float* __restrict__ out)
{
    const int row = blockIdx.x;
    const float4* p4 = (const float4*)(y + (size_t)row * H_);
    const int tid = threadIdx.x;
    __shared__ float rs[256], rq[256];

    const float4 v = p4[tid];
    rs[tid] = v.x + v.y + v.z + v.w;
    rq[tid] = v.x * v.x + v.y * v.y + v.z * v.z + v.w * v.w;
    __syncthreads();
    for (int o = 128; o > 0; o >>= 1) {
        if (tid < o) { rs[tid] += rs[tid + o]; rq[tid] += rq[tid + o]; }
        __syncthreads();
    }
    const float mu  = rs[0] * (1.0f / H_);
    const float var = rq[0] * (1.0f / H_) - mu * mu;
    const float inv = rsqrtf(var + 1e-5f);
    const float4 g = ((const float4*)gamma)[tid];
    const float4 b = ((const float4*)beta)[tid];
    float4 o;
    o.x = (v.x - mu) * inv * g.x + b.x;
    o.y = (v.y - mu) * inv * g.y + b.y;
    o.z = (v.z - mu) * inv * g.z + b.z;
    o.w = (v.w - mu) * inv * g.w + b.w;
    ((float4*)(out + (size_t)row * H_))[tid] = o;
}

// ---------------------------------------------------------------------------
// Launch   (harness issues 2 launches first; ncu -s 5 -c 1 captures overall
//           launch #6 = OUR launch #4 = the V^T tgemm)
// ---------------------------------------------------------------------------
extern "C" void kernel_launch(void* const* d_in, const int* in_sizes, int n_in,
                              void* d_out, int out_size)
{
    const float* x     = (const float*)d_in[0];
    const float* mask  = (const float*)d_in[1];
    const float* qW    = (const float*)d_in[2];
    const float* qb    = (const float*)d_in[3];
    const float* kW    = (const float*)d_in[4];
    const float* kb    = (const float*)d_in[5];
    const float* vW    = (const float*)d_in[6];
    const float* vb    = (const float*)d_in[7];
    const float* w1    = (const float*)d_in[8];
    const float* b1    = (const float*)d_in[9];
    const float* w2    = (const float*)d_in[10];
    const float* b2    = (const float*)d_in[11];
    const float* gamma = (const float*)d_in[12];
    const float* beta  = (const float*)d_in[13];
    float* out = (float*)d_out;

    __half *xh, *qk, *s16, *a16, *h16, *wqkt, *wvt, *w1t, *w2t, *vt;
    float *yp, *qkb;
    cudaGetSymbolAddress((void**)&xh, g_xh);
    cudaGetSymbolAddress((void**)&qk, g_qk);
    cudaGetSymbolAddress((void**)&s16, g_s16);
    cudaGetSymbolAddress((void**)&a16, g_a16);
    cudaGetSymbolAddress((void**)&h16, g_h16);
    cudaGetSymbolAddress((void**)&yp, g_y);
    cudaGetSymbolAddress((void**)&wqkt, g_wqkt);
    cudaGetSymbolAddress((void**)&wvt, g_wvt);
    cudaGetSymbolAddress((void**)&w1t, g_w1t);
    cudaGetSymbolAddress((void**)&w2t, g_w2t);
    cudaGetSymbolAddress((void**)&vt, g_vt);
    cudaGetSymbolAddress((void**)&qkb, g_qkb);

    cudaFuncSetAttribute((const void*)tgemm<true,  false, false, false, true,  false>,
                         cudaFuncAttributeMaxDynamicSharedMemorySize, SMEM_B);
    cudaFuncSetAttribute((const void*)tgemm<false, false, false, true,  true,  false>,
                         cudaFuncAttributeMaxDynamicSharedMemorySize, SMEM_B);
    cudaFuncSetAttribute((const void*)tgemm<false, false, false, false, true,  false>,
                         cudaFuncAttributeMaxDynamicSharedMemorySize, SMEM_B);
    cudaFuncSetAttribute((const void*)tgemm<true,  true,  false, false, true,  false>,
                         cudaFuncAttributeMaxDynamicSharedMemorySize, SMEM_B);
    cudaFuncSetAttribute((const void*)tgemm<true,  false, true,  false, false, true >,
                         cudaFuncAttributeMaxDynamicSharedMemorySize, SMEM_B);

    const dim3 blk(256);
    const dim3 gblk(128);

    // 1: x -> fp16
    tohalf_k<<<(NTOK * H_) / 1024, blk>>>(x, xh);
    // 2: transpose vW (needed by #4)
    transpose_k<<<dim3(H_ / 32, H_ / 32, 1), blk>>>(vW, wvt, H_, H_);
    // 3: transpose qW (prep for #7)
    transpose_k<<<dim3(H_ / 32, H_ / 32, 1), blk>>>(qW, wqkt, H_, H_);

    // 4: V^T = wv^T @ x^T + vb -> vt fp16 [1024, 8192]   <-- ncu capture
    tgemm<false, false, false, true, true, false>
        <<<dim3(NTOK / 128, H_ / 128, 1), gblk, SMEM_B>>>(
        wvt, xh, vb, nullptr, vt, nullptr,
        H_, H_, H_, NTOK, 0, 0, 0, 1.0f);

    // 5: transpose kW; 6: concat q/k biases
    transpose_k<<<dim3(H_ / 32, H_ / 32, 1), blk>>>(kW, wqkt + (size_t)H_ * H_, H_, H_);
    catbias_k<<<(2 * H_) / 256, blk>>>(qb, kb, qkb);

    // 7: fused Q|K projection -> qk fp16 [8192, 2048]
    tgemm<true, false, false, false, true, false>
        <<<dim3(2 * H_ / 128, NTOK / 128, 1), gblk, SMEM_B>>>(
        xh, wqkt, qkb, nullptr, qk, nullptr,
        H_, H_, H_, 2 * H_, 0, 0, 0, 1.0f);

    // 8,9: FFN weight transposes
    transpose_k<<<dim3(F_ / 32, H_ / 32, 1), blk>>>(w1, w1t, H_, F_);
    transpose_k<<<dim3(H_ / 32, F_ / 32, 1), blk>>>(w2, w2t, F_, H_);

    // 10: scores = q @ k^T / sqrt(H) -> s16, per batch
    tgemm<false, false, false, false, true, false>
        <<<dim3(S_ / 128, S_ / 128, B_), gblk, SMEM_B>>>(
        qk, qk + H_, nullptr, nullptr, s16, nullptr,
        H_, 2 * H_, 2 * H_, S_,
        (size_t)S_ * 2 * H_, (size_t)S_ * 2 * H_, (size_t)S_ * S_, 0.03125f);

    // 11: softmax in place on fp16
    softmax_k<<<NTOK, blk>>>(s16, mask);

    // 12: attn = a @ v -> a16 fp16, per batch
    tgemm<false, false, false, false, true, false>
        <<<dim3(H_ / 128, S_ / 128, B_), gblk, SMEM_B>>>(
        s16, vt, nullptr, nullptr, a16, nullptr,
        S_, S_, NTOK, H_,
        (size_t)S_ * S_, (size_t)S_, (size_t)S_ * H_, 1.0f);

    // 13: FFN1: h = relu(attn @ w1 + b1) -> h16
    tgemm<true, true, false, false, true, false>
        <<<dim3(F_ / 128, NTOK / 128, 1), gblk, SMEM_B>>>(
        a16, w1t, b1, nullptr, h16, nullptr,
        H_, H_, H_, F_, 0, 0, 0, 1.0f);

    // 14: FFN2: y = attn16 + h @ w2 + b2 -> fp32
    tgemm<true, false, true, false, false, true>
        <<<dim3(H_ / 128, NTOK / 128, 1), gblk, SMEM_B>>>(
        h16, w2t, b2, a16, nullptr, yp,
        F_, F_, F_, H_, 0, 0, 0, 1.0f);

    // 15: LayerNorm
    ln_k<<<NTOK, blk>>>(yp, gamma, beta, out);
}

// round 14
// speedup vs baseline: 1.1093x; 1.1093x over previous
#include <cuda_runtime.h>
#include <cuda_fp16.h>
#include <cstdint>
#include <math.h>

#define B_   4
#define S_   2048
#define H_   1024
#define F_   4096
#define NTOK (B_ * S_)   // 8192

// ---------------------------------------------------------------------------
// Scratch (static device globals)
// ---------------------------------------------------------------------------
__device__ __half g_xh[(size_t)NTOK * H_];
__device__ __half g_qk[(size_t)NTOK * 2 * H_];     // [8192, 2048]: q | k
__device__ __half g_s16[(size_t)B_ * S_ * S_];
__device__ __half g_a16[(size_t)NTOK * H_];
__device__ __half g_h16[(size_t)NTOK * F_];
__device__ float  g_y[(size_t)NTOK * H_];
__device__ __half g_wqkt[(size_t)2 * H_ * H_];     // [2048, 1024]: wq^T | wk^T
__device__ __half g_wvt[(size_t)H_ * H_];
__device__ __half g_w1t[(size_t)H_ * F_];
__device__ __half g_w2t[(size_t)F_ * H_];
__device__ __half g_vt[(size_t)H_ * NTOK];         // [1024, 8192] V^T, all batches
__device__ float  g_qkb[2 * H_];

// ---------------------------------------------------------------------------
// Helpers
// ---------------------------------------------------------------------------
__device__ __forceinline__ uint32_t smem_u32(const void* p) {
    uint32_t a;
    asm("{ .reg .u64 t; cvta.to.shared.u64 t, %1; cvt.u32.u64 %0, t; }" : "=r"(a) : "l"(p));
    return a;
}
__device__ __forceinline__ void cp16(uint32_t s, const void* g) {
    asm volatile("cp.async.cg.shared.global [%0], [%1], 16;" :: "r"(s), "l"(g) : "memory");
}
#define CP_COMMIT() asm volatile("cp.async.commit_group;" ::: "memory")
#define CP_WAIT2()  asm volatile("cp.async.wait_group 2;" ::: "memory")

__device__ __forceinline__ void mma16(float c[4], const uint32_t a[4], const uint32_t b[2]) {
    asm volatile("mma.sync.aligned.m16n8k16.row.col.f32.f16.f16.f32 "
                 "{%0,%1,%2,%3}, {%4,%5,%6,%7}, {%8,%9}, {%0,%1,%2,%3};"
                 : "+f"(c[0]), "+f"(c[1]), "+f"(c[2]), "+f"(c[3])
                 : "r"(a[0]), "r"(a[1]), "r"(a[2]), "r"(a[3]), "r"(b[0]), "r"(b[1]));
}
__device__ __forceinline__ void ldsm4(uint32_t r[4], uint32_t addr) {
    asm volatile("ldmatrix.sync.aligned.m8n8.x4.shared.b16 {%0,%1,%2,%3}, [%4];"
                 : "=r"(r[0]), "=r"(r[1]), "=r"(r[2]), "=r"(r[3]) : "r"(addr));
}

// ---------------------------------------------------------------------------
// FP16 tensor-core GEMM (fp32 accum), cp.async 4-stage pipeline, ldmatrix:
//   acc = alpha * A[M,K] * Bw[N,K]^T (+bias[N]) (+biasM[M]) (+res fp16) (relu)
//   outputs: C16 (fp16) if O16, C32 (fp32) if O32
// CTA tile 128x128, BK=32, 4 warps (2x2), warp tile 64x64, 128 threads,
// 2 CTAs/SM. M,N mult of 128, K mult of 32. Batched over blockIdx.z.
// Smem: 4 stages x (128+128) rows x 80 B = 81920 B.
// ---------------------------------------------------------------------------
#define ROWB 80                                  // bytes per smem row (32 fp16 + 8 pad)
#define STAGE_B  ((128 + 128) * ROWB)            // 20480
#define NSTAGE 4
#define SMEM_B   (NSTAGE * STAGE_B)              // 81920

template <bool BIAS, bool RELU, bool RES, bool BIASM, bool O16, bool O32>
__global__ __launch_bounds__(128, 2) void tgemm(
    const __half* __restrict__ A, const __half* __restrict__ Bw,
    const float* __restrict__ bias, const __half* __restrict__ res,
    __half* __restrict__ C16, float* __restrict__ C32,
    int K, int lda, int ldb, int ldc,
    size_t sA, size_t sB, size_t sC, float alpha)
{
    extern __shared__ uint32_t smem[];
    const uint32_t sbase = smem_u32(smem);

    const int tid  = threadIdx.x;
    const int wid  = tid >> 5, lane = tid & 31;
    const int g    = lane >> 2, t4 = lane & 3;
    const int warpM = wid >> 1, warpN = wid & 1;

    const int z = blockIdx.z;
    A  += (size_t)z * sA;
    Bw += (size_t)z * sB;
    const __half* Rp = RES ? (res + (size_t)z * sC) : nullptr;

    const int n0 = blockIdx.x << 7, m0 = blockIdx.y << 7;
    const __half* Ap = A  + (size_t)m0 * lda;
    const __half* Bp = Bw + (size_t)n0 * ldb;

    const int KT = K >> 5;

    auto issue = [&](int kt) {
        const uint32_t s = sbase + (uint32_t)(kt % NSTAGE) * STAGE_B;
        const int kb = kt << 5;
#pragma unroll
        for (int j = 0; j < 4; j++) {            // A: 128 rows x 4 chunks = 512
            const int c = tid + (j << 7);
            const int row = c >> 2, ch = c & 3;
            cp16(s + (uint32_t)(row * ROWB + ch * 16),
                 Ap + (size_t)row * lda + kb + ch * 8);
        }
        const uint32_t sB2 = s + (uint32_t)(128 * ROWB);
#pragma unroll
        for (int j = 0; j < 4; j++) {            // B: 128 rows x 4 chunks = 512
            const int c = tid + (j << 7);
            const int row = c >> 2, ch = c & 3;
            cp16(sB2 + (uint32_t)(row * ROWB + ch * 16),
                 Bp + (size_t)row * ldb + kb + ch * 8);
        }
    };

    // ldmatrix per-lane source offsets (bytes)
    const int aRowOff = (((lane >> 3) & 1) << 3) + (lane & 7);
    const int aKb     = (lane >> 4) << 4;                 // 0 or 16 bytes
    const int bRowOff = ((lane >> 4) << 3) + (lane & 7);
    const int bKb     = ((lane >> 3) & 1) << 4;

    const uint32_t aLane = sbase + (uint32_t)((warpM * 64 + aRowOff) * ROWB + aKb);
    const uint32_t bLane = sbase + (uint32_t)(128 * ROWB)
        + (uint32_t)((warpN * 64 + bRowOff) * ROWB + bKb);

    float acc[4][8][4];
#pragma unroll
    for (int mt = 0; mt < 4; mt++)
#pragma unroll
        for (int nt = 0; nt < 8; nt++)
#pragma unroll
            for (int i = 0; i < 4; i++) acc[mt][nt][i] = 0.0f;

    issue(0); CP_COMMIT();
    issue(1); CP_COMMIT();
    issue(2); CP_COMMIT();

    for (int kt = 0; kt < KT; kt++) {
        CP_WAIT2();
        __syncthreads();

        if (kt + 3 < KT) issue(kt + 3);
        CP_COMMIT();

        const uint32_t stOff = (uint32_t)((kt % NSTAGE) * STAGE_B);

        // hoist ALL fragment loads (both k16 slices) ahead of the MMA burst
        uint32_t afr[2][4][4], bfr[2][8][2];
#pragma unroll
        for (int ks = 0; ks < 2; ks++) {
#pragma unroll
            for (int mt = 0; mt < 4; mt++)
                ldsm4(afr[ks][mt], aLane + stOff + (uint32_t)(mt * 16 * ROWB + ks * 32));
#pragma unroll
            for (int p = 0; p < 4; p++) {
                uint32_t r[4];
                ldsm4(r, bLane + stOff + (uint32_t)(p * 16 * ROWB + ks * 32));
                bfr[ks][2 * p][0] = r[0]; bfr[ks][2 * p][1] = r[1];
                bfr[ks][2 * p + 1][0] = r[2]; bfr[ks][2 * p + 1][1] = r[3];
            }
        }
#pragma unroll
        for (int ks = 0; ks < 2; ks++)
#pragma unroll
            for (int mt = 0; mt < 4; mt++)
#pragma unroll
                for (int nt = 0; nt < 8; nt++)
                    mma16(acc[mt][nt], afr[ks][mt], bfr[ks][nt]);
    }

    // --- fused epilogue ---
    __half* Cp16 = O16 ? (C16 + (size_t)z * sC) : nullptr;
    float*  Cp32 = O32 ? (C32 + (size_t)z * sC) : nullptr;
    const int rbase = m0 + warpM * 64;
    const int cbase = n0 + warpN * 64;
#pragma unroll
    for (int mt = 0; mt < 4; mt++) {
#pragma unroll
        for (int nt = 0; nt < 8; nt++) {
            const int col = cbase + nt * 8 + (t4 << 1);
            float bx = 0.f, by = 0.f;
            if (BIAS) {
                float2 bb = *(const float2*)(bias + col);
                bx = bb.x; by = bb.y;
            }
#pragma unroll
            for (int hh = 0; hh < 2; hh++) {
                const int row = rbase + mt * 16 + g + hh * 8;
                float v0 = acc[mt][nt][hh * 2 + 0] * alpha;
                float v1 = acc[mt][nt][hh * 2 + 1] * alpha;
                if (BIAS) { v0 += bx; v1 += by; }
                if (BIASM) { const float bm = bias[row]; v0 += bm; v1 += bm; }
                if (RES) {
                    const __half2 rr = *(const __half2*)(Rp + (size_t)row * ldc + col);
                    const float2 rf = __half22float2(rr);
                    v0 += rf.x; v1 += rf.y;
                }
                if (RELU) { v0 = fmaxf(v0, 0.f); v1 = fmaxf(v1, 0.f); }
                if (O16)
                    *(__half2*)(Cp16 + (size_t)row * ldc + col) = __floats2half2_rn(v0, v1);
                if (O32) {
                    float2 o; o.x = v0; o.y = v1;
                    *(float2*)(Cp32 + (size_t)row * ldc + col) = o;
                }
            }
        }
    }
}

// ---------------------------------------------------------------------------
// x (fp32) -> fp16
// ---------------------------------------------------------------------------
__global__ __launch_bounds__(256) void tohalf_k(const float* __restrict__ in,
                                                __half* __restrict__ out)
{
    const size_t i = ((size_t)blockIdx.x * 256 + threadIdx.x) * 4;
    float4 v = *(const float4*)(in + i);
    __half2* o = (__half2*)(out + i);
    o[0] = __floats2half2_rn(v.x, v.y);
    o[1] = __floats2half2_rn(v.z, v.w);
}

// ---------------------------------------------------------------------------
// Concat two H_-vectors (bias) into one 2H_ vector
// ---------------------------------------------------------------------------
__global__ __launch_bounds__(256) void catbias_k(const float* __restrict__ a,
                                                 const float* __restrict__ b,
                                                 float* __restrict__ out)
{
    const int i = blockIdx.x * 256 + threadIdx.x;
    out[i] = (i < H_) ? a[i] : b[i - H_];
}

// ---------------------------------------------------------------------------
// Transpose fp32 src [R,C] -> fp16 dst [C,R]
// ---------------------------------------------------------------------------
__global__ __launch_bounds__(256) void transpose_k(const float* __restrict__ src,
                                                   __half* __restrict__ dst, int R, int C)
{
    __shared__ float t[32][33];
    const int bx = blockIdx.x << 5, by = blockIdx.y << 5;
    const int tx = threadIdx.x & 31, ty = (threadIdx.x >> 5) << 2;
#pragma unroll
    for (int j = 0; j < 4; j++)
        t[ty + j][tx] = src[(size_t)(by + ty + j) * C + bx + tx];
    __syncthreads();
#pragma unroll
    for (int j = 0; j < 4; j++)
        dst[(size_t)(bx + ty + j) * R + by + tx] = __float2half_rn(t[tx][ty + j]);
}

// ---------------------------------------------------------------------------
// Row softmax (S_ wide) on fp16 scores with fp32 mask; in-place fp16
// ---------------------------------------------------------------------------
__global__ __launch_bounds__(256) void softmax_k(__half* __restrict__ s,
                                                 const float* __restrict__ mask)
{
    const int row = blockIdx.x;
    const int q   = row & (S_ - 1);
    __half2* p = (__half2*)(s + (size_t)row * S_);
    const float* mrow = mask + (size_t)q * S_;
    const int tid = threadIdx.x;
    __shared__ float red[256];

    float vals[8];
    float vmax = -3.0e38f;
#pragma unroll
    for (int i = 0; i < 4; i++) {
        const int idx = tid + i * 256;          // half2 index
        const float2 v2 = __half22float2(p[idx]);
        const float2 m2 = *(const float2*)(mrow + idx * 2);
        const float a = v2.x + m2.x, b = v2.y + m2.y;
        vals[2 * i] = a; vals[2 * i + 1] = b;
        vmax = fmaxf(vmax, fmaxf(a, b));
    }
    red[tid] = vmax; __syncthreads();
    for (int o = 128; o > 0; o >>= 1) {
        if (tid < o) red[tid] = fmaxf(red[tid], red[tid + o]);
        __syncthreads();
    }
    vmax = red[0]; __syncthreads();
    float sum = 0.0f;
#pragma unroll
    for (int i = 0; i < 8; i++) { const float e = __expf(vals[i] - vmax); vals[i] = e; sum += e; }
    red[tid] = sum; __syncthreads();
    for (int o = 128; o > 0; o >>= 1) {
        if (tid < o) red[tid] += red[tid + o];
        __syncthreads();
    }
    const float inv = 1.0f / red[0];
#pragma unroll
    for (int i = 0; i < 4; i++)
        p[tid + i * 256] = __floats2half2_rn(vals[2 * i] * inv, vals[2 * i + 1] * inv);
}

// ---------------------------------------------------------------------------
// LayerNorm (H_=1024)
// ---------------------------------------------------------------------------
__global__ __launch_bounds__(256) void ln_k(const float* __restrict__ y,
                                            const float* __restrict__ gamma,
                                            const float* __restrict__ beta,
                                            float* __restrict__ out)
{
    const int row = blockIdx.x;
    const float4* p4 = (const float4*)(y + (size_t)row * H_);
    const int tid = threadIdx.x;
    __shared__ float rs[256], rq[256];

    const float4 v = p4[tid];
    rs[tid] = v.x + v.y + v.z + v.w;
    rq[tid] = v.x * v.x + v.y * v.y + v.z * v.z + v.w * v.w;
    __syncthreads();
    for (int o = 128; o > 0; o >>= 1) {
        if (tid < o) { rs[tid] += rs[tid + o]; rq[tid] += rq[tid + o]; }
        __syncthreads();
    }
    const float mu  = rs[0] * (1.0f / H_);
    const float var = rq[0] * (1.0f / H_) - mu * mu;
    const float inv = rsqrtf(var + 1e-5f);
    const float4 g = ((const float4*)gamma)[tid];
    const float4 b = ((const float4*)beta)[tid];
    float4 o;
    o.x = (v.x - mu) * inv * g.x + b.x;
    o.y = (v.y - mu) * inv * g.y + b.y;
    o.z = (v.z - mu) * inv * g.z + b.z;
    o.w = (v.w - mu) * inv * g.w + b.w;
    ((float4*)(out + (size_t)row * H_))[tid] = o;
}

// ---------------------------------------------------------------------------
// Launch — two-stream fork/join: V^T GEMM + FFN weight transposes run on a
// side stream, hidden under the QK -> scores -> softmax critical path.
// Stream/events are created lazily on the first (uncaptured correctness)
// call and reused during capture; the side stream is joined via event wait
// before attn, so capture ends fully joined.
// (harness issues 2 launches first; ncu -s 5 -c 1 captures overall launch
//  #6 = OUR 4th kernel submission = the V^T tgemm)
// ---------------------------------------------------------------------------
extern "C" void kernel_launch(void* const* d_in, const int* in_sizes, int n_in,
                              void* d_out, int out_size)
{
    const float* x     = (const float*)d_in[0];
    const float* mask  = (const float*)d_in[1];
    const float* qW    = (const float*)d_in[2];
    const float* qb    = (const float*)d_in[3];
    const float* kW    = (const float*)d_in[4];
    const float* kb    = (const float*)d_in[5];
    const float* vW    = (const float*)d_in[6];
    const float* vb    = (const float*)d_in[7];
    const float* w1    = (const float*)d_in[8];
    const float* b1    = (const float*)d_in[9];
    const float* w2    = (const float*)d_in[10];
    const float* b2    = (const float*)d_in[11];
    const float* gamma = (const float*)d_in[12];
    const float* beta  = (const float*)d_in[13];
    float* out = (float*)d_out;

    __half *xh, *qk, *s16, *a16, *h16, *wqkt, *wvt, *w1t, *w2t, *vt;
    float *yp, *qkb;
    cudaGetSymbolAddress((void**)&xh, g_xh);
    cudaGetSymbolAddress((void**)&qk, g_qk);
    cudaGetSymbolAddress((void**)&s16, g_s16);
    cudaGetSymbolAddress((void**)&a16, g_a16);
    cudaGetSymbolAddress((void**)&h16, g_h16);
    cudaGetSymbolAddress((void**)&yp, g_y);
    cudaGetSymbolAddress((void**)&wqkt, g_wqkt);
    cudaGetSymbolAddress((void**)&wvt, g_wvt);
    cudaGetSymbolAddress((void**)&w1t, g_w1t);
    cudaGetSymbolAddress((void**)&w2t, g_w2t);
    cudaGetSymbolAddress((void**)&vt, g_vt);
    cudaGetSymbolAddress((void**)&qkb, g_qkb);

    cudaFuncSetAttribute((const void*)tgemm<true,  false, false, false, true,  false>,
                         cudaFuncAttributeMaxDynamicSharedMemorySize, SMEM_B);
    cudaFuncSetAttribute((const void*)tgemm<false, false, false, true,  true,  false>,
                         cudaFuncAttributeMaxDynamicSharedMemorySize, SMEM_B);
    cudaFuncSetAttribute((const void*)tgemm<false, false, false, false, true,  false>,
                         cudaFuncAttributeMaxDynamicSharedMemorySize, SMEM_B);
    cudaFuncSetAttribute((const void*)tgemm<true,  true,  false, false, true,  false>,
                         cudaFuncAttributeMaxDynamicSharedMemorySize, SMEM_B);
    cudaFuncSetAttribute((const void*)tgemm<true,  false, true,  false, false, true >,
                         cudaFuncAttributeMaxDynamicSharedMemorySize, SMEM_B);

    // Lazy one-time stream/event creation (first call is the uncaptured
    // correctness run; capture call reuses these host objects).
    static cudaStream_t s1 = nullptr;
    static cudaEvent_t eXh = nullptr, eSide = nullptr;
    if (s1 == nullptr) {
        cudaStreamCreateWithFlags(&s1, cudaStreamNonBlocking);
        cudaEventCreateWithFlags(&eXh, cudaEventDisableTiming);
        cudaEventCreateWithFlags(&eSide, cudaEventDisableTiming);
    }

    const dim3 blk(256);
    const dim3 gblk(128);

    // #1 (s0): x -> fp16
    tohalf_k<<<(NTOK * H_) / 1024, blk>>>(x, xh);
    cudaEventRecord(eXh, 0);

    // #2 (s1): transpose vW (input-only dep)
    transpose_k<<<dim3(H_ / 32, H_ / 32, 1), blk, 0, s1>>>(vW, wvt, H_, H_);
    // #3 (s0): transpose qW
    transpose_k<<<dim3(H_ / 32, H_ / 32, 1), blk>>>(qW, wqkt, H_, H_);

    // s1 forks from s0 after xh is ready
    cudaStreamWaitEvent(s1, eXh, 0);

    // #4 (s1): V^T = wv^T @ x^T + vb -> vt fp16 [1024, 8192]   <-- ncu capture
    tgemm<false, false, false, true, true, false>
        <<<dim3(NTOK / 128, H_ / 128, 1), gblk, SMEM_B, s1>>>(
        wvt, xh, vb, nullptr, vt, nullptr,
        H_, H_, H_, NTOK, 0, 0, 0, 1.0f);

    // #5,#6 (s1): FFN weight transposes (needed only at FFN1/FFN2)
    transpose_k<<<dim3(F_ / 32, H_ / 32, 1), blk, 0, s1>>>(w1, w1t, H_, F_);
    transpose_k<<<dim3(H_ / 32, F_ / 32, 1), blk, 0, s1>>>(w2, w2t, F_, H_);
    cudaEventRecord(eSide, s1);

    // #7 (s0): transpose kW; #8: concat q/k biases
    transpose_k<<<dim3(H_ / 32, H_ / 32, 1), blk>>>(kW, wqkt + (size_t)H_ * H_, H_, H_);
    catbias_k<<<(2 * H_) / 256, blk>>>(qb, kb, qkb);

    // #9 (s0): fused Q|K projection -> qk fp16 [8192, 2048]
    tgemm<true, false, false, false, true, false>
        <<<dim3(2 * H_ / 128, NTOK / 128, 1), gblk, SMEM_B>>>(
        xh, wqkt, qkb, nullptr, qk, nullptr,
        H_, H_, H_, 2 * H_, 0, 0, 0, 1.0f);

    // #10 (s0): scores = q @ k^T / sqrt(H) -> s16, per batch
    tgemm<false, false, false, false, true, false>
        <<<dim3(S_ / 128, S_ / 128, B_), gblk, SMEM_B>>>(
        qk, qk + H_, nullptr, nullptr, s16, nullptr,
        H_, 2 * H_, 2 * H_, S_,
        (size_t)S_ * 2 * H_, (size_t)S_ * 2 * H_, (size_t)S_ * S_, 0.03125f);

    // #11 (s0): softmax in place on fp16
    softmax_k<<<NTOK, blk>>>(s16, mask);

    // join: attn needs vt (and FFN needs w1t/w2t, already ordered before eSide)
    cudaStreamWaitEvent(0, eSide, 0);

    // #12 (s0): attn = a @ v -> a16 fp16, per batch
    tgemm<false, false, false, false, true, false>
        <<<dim3(H_ / 128, S_ / 128, B_), gblk, SMEM_B>>>(
        s16, vt, nullptr, nullptr, a16, nullptr,
        S_, S_, NTOK, H_,
        (size_t)S_ * S_, (size_t)S_, (size_t)S_ * H_, 1.0f);

    // #13 (s0): FFN1: h = relu(attn @ w1 + b1) -> h16
    tgemm<true, true, false, false, true, false>
        <<<dim3(F_ / 128, NTOK / 128, 1), gblk, SMEM_B>>>(
        a16, w1t, b1, nullptr, h16, nullptr,
        H_, H_, H_, F_, 0, 0, 0, 1.0f);

    // #14 (s0): FFN2: y = attn16 + h @ w2 + b2 -> fp32
    tgemm<true, false, true, false, false, true>
        <<<dim3(H_ / 128, NTOK / 128, 1), gblk, SMEM_B>>>(
        h16, w2t, b2, a16, nullptr, yp,
        F_, F_, F_, H_, 0, 0, 0, 1.0f);

    // #15 (s0): LayerNorm
    ln_k<<<NTOK, blk>>>(yp, gamma, beta, out);
}